// round 12
// baseline (speedup 1.0000x reference)
#include <cuda_runtime.h>
#include <cstdint>

#define VS 100
#define BATCH 8
#define NUM_COORDS 65536
#define NPTS (BATCH * NUM_COORDS)          // 524288
#define NCELLS (BATCH * VS * VS * VS)      // 8,000,000
#define NF4 (NCELLS * 10 / 4)              // 20,000,000 float4s of output

// Scratch: zero-initialized at module load. occupied_kernel re-zeroes the
// cells it consumes and reset_kernel clears the worklist counter, so every
// graph replay starts from the same state.
// g_sum ch0..5 = sums(x,y,z,f0,f1,f2), ch6 = count (election), ch7 = 0.
__device__ float g_sum[(size_t)NCELLS * 8];   // 256 MB
__device__ int   g_list[NPTS];                // 2 MB worklist of occupied cells
__device__ int   g_count;                     // worklist size

// ---------------------------------------------------------------------------
// 1) Background pattern writer: the whole 320 MB output, no loads.
//    Record = [m0..m5, i*.01, j*.01, k*.01, occ]; background = zeros + index
//    grid + occ=0. Two cells = 20 floats = 5 float4s; thread handles one f4.
__global__ void __launch_bounds__(256) stream_kernel(float4* __restrict__ out4)
{
    int F = blockIdx.x * 256 + threadIdx.x;   // < NF4 (grid exact)
    int G = F / 5;                            // 2-cell chunk id
    int m = F - G * 5;                        // position within chunk
    int cell = 2 * G + (m == 4 ? 1 : 0);      // which cell this f4 touches

    // Decode (i, j, k) within the batch's 100^3 block.
    int k = cell % VS;
    int t = cell / VS;
    int j = t % VS;
    int i = (t / VS) % VS;
    float fi = (float)i * 0.01f;
    float fj = (float)j * 0.01f;
    float fk = (float)k * 0.01f;

    float4 v = make_float4(0.f, 0.f, 0.f, 0.f);
    if (m == 1) { v.z = fi; v.w = fj; }                  // floats 4-7 of cell0
    else if (m == 2) { v.x = fk; }                       // floats 8-11
    else if (m == 4) { v.x = fi; v.y = fj; v.z = fk; }   // floats 16-19 of cell1

    out4[F] = v;
}

// ---------------------------------------------------------------------------
// 2) Scatter with first-writer election -> worklist.
__global__ void __launch_bounds__(256) scatter_kernel(
    const float* __restrict__ coords,
    const float* __restrict__ feats)
{
    int idx = blockIdx.x * blockDim.x + threadIdx.x;
    if (idx >= NPTS) return;

    float x = coords[idx * 3 + 0];
    float y = coords[idx * 3 + 1];
    float z = coords[idx * 3 + 2];

    // Reference constants collapse in f32: res = denom = 0.01f, shift = -0.01f
    const float shift = 0.01f;
    const float denom = 0.01f;
    int ix = (int)floorf((x + shift) / denom);
    int iy = (int)floorf((y + shift) / denom);
    int iz = (int)floorf((z + shift) / denom);

    if (ix < 1 || ix > VS || iy < 1 || iy > VS || iz < 1 || iz > VS) return;

    int b = idx >> 16;  // NUM_COORDS = 65536
    int cell = ((b * VS + (ix - 1)) * VS + (iy - 1)) * VS + (iz - 1);

    float f0 = feats[idx * 3 + 0];
    float f1 = feats[idx * 3 + 1];
    float f2 = feats[idx * 3 + 2];

    float* s = &g_sum[(size_t)cell * 8];
    asm volatile("red.global.add.v4.f32 [%0], {%1, %2, %3, %4};"
                 :: "l"(s), "f"(x), "f"(y), "f"(z), "f"(f0) : "memory");
    asm volatile("red.global.add.v2.f32 [%0], {%1, %2};"
                 :: "l"(s + 4), "f"(f1), "f"(f2) : "memory");
    // Count + first-writer election (exact: small integers accumulate exactly).
    float old = atomicAdd(s + 6, 1.0f);
    if (old == 0.0f) {
        int pos = atomicAdd(&g_count, 1);
        g_list[pos] = cell;
    }
}

// ---------------------------------------------------------------------------
// 3) Occupied cells only: scatter means into the pre-written background.
__global__ void __launch_bounds__(256) occupied_kernel(float* __restrict__ out)
{
    int idx = blockIdx.x * 256 + threadIdx.x;
    if (idx >= g_count) return;

    int cell = g_list[idx];
    float4* sp = (float4*)&g_sum[(size_t)cell * 8];
    float4 a  = sp[0];
    float4 b4 = sp[1];
    float cnt = b4.z;

    float* o = out + (size_t)cell * 10;
    ((float2*)o)[0] = make_float2(a.x / cnt, a.y / cnt);
    ((float2*)o)[1] = make_float2(a.z / cnt, a.w / cnt);
    ((float2*)o)[2] = make_float2(b4.x / cnt, b4.y / cnt);
    o[9] = 1.0f;   // occupied

    // Self-clean scratch for the next graph replay.
    float4 z4 = make_float4(0.f, 0.f, 0.f, 0.f);
    sp[0] = z4;
    sp[1] = z4;
}

// 4) Reset worklist counter for the next replay.
__global__ void reset_kernel() { g_count = 0; }

// ---------------------------------------------------------------------------
extern "C" void kernel_launch(void* const* d_in, const int* in_sizes, int n_in,
                              void* d_out, int out_size)
{
    const float* coords = (const float*)d_in[0];
    const float* feats  = (const float*)d_in[1];
    float* out = (float*)d_out;

    // Create side stream + events once; reuse on every call (deterministic).
    static cudaStream_t s2 = nullptr;
    static cudaEvent_t eFork = nullptr, eJoin = nullptr;
    if (!s2) {
        cudaStreamCreateWithFlags(&s2, cudaStreamNonBlocking);
        cudaEventCreateWithFlags(&eFork, cudaEventDisableTiming);
        cudaEventCreateWithFlags(&eJoin, cudaEventDisableTiming);
    }

    // Fork: stream_kernel (input-independent 320 MB write) runs concurrently
    // with scatter_kernel; occupied_kernel joins both branches.
    cudaEventRecord(eFork, 0);
    cudaStreamWaitEvent(s2, eFork, 0);
    stream_kernel<<<NF4 / 256, 256, 0, s2>>>((float4*)out);  // 78125 blocks
    cudaEventRecord(eJoin, s2);

    scatter_kernel<<<NPTS / 256, 256>>>(coords, feats);      // 2048 blocks

    cudaStreamWaitEvent(0, eJoin, 0);
    occupied_kernel<<<NPTS / 256, 256>>>(out);               // bound: g_count <= NPTS
    reset_kernel<<<1, 1>>>();
}

// round 13
// speedup vs baseline: 1.8974x; 1.8974x over previous
#include <cuda_runtime.h>
#include <cstdint>

#define VS 100
#define BATCH 8
#define NUM_COORDS 65536
#define NPTS (BATCH * NUM_COORDS)          // 524288
#define NCELLS (BATCH * VS * VS * VS)      // 8,000,000

#define GROUPS 10                           // cells per block = GROUPS*256 = 2560
#define CPB (GROUPS * 256)
#define NBLK (NCELLS / CPB)                 // 3125, exact
#define NBUF 3                              // triple-buffered TMA stores

// Scratch: zero-initialized at module load; finalize re-zeroes exactly the
// occupied cells it consumes -> graph replays deterministic, no clear pass.
// g_sum ch0..5 = sums(x,y,z,f0,f1,f2), ch6 = count, ch7 = 0.
__device__ float g_sum[(size_t)NCELLS * 8];   // 256 MB
__device__ unsigned char g_flag[NCELLS];      // 8 MB occupancy flags

__global__ void __launch_bounds__(256) scatter_kernel(
    const float* __restrict__ coords,
    const float* __restrict__ feats)
{
    int idx = blockIdx.x * blockDim.x + threadIdx.x;
    if (idx >= NPTS) return;

    float x = coords[idx * 3 + 0];
    float y = coords[idx * 3 + 1];
    float z = coords[idx * 3 + 2];

    // Reference constants collapse in f32: res = denom = 0.01f, shift = -0.01f
    const float shift = 0.01f;
    const float denom = 0.01f;
    int ix = (int)floorf((x + shift) / denom);
    int iy = (int)floorf((y + shift) / denom);
    int iz = (int)floorf((z + shift) / denom);

    if (ix < 1 || ix > VS || iy < 1 || iy > VS || iz < 1 || iz > VS) return;

    int b = idx >> 16;  // NUM_COORDS = 65536
    int cell = ((b * VS + (ix - 1)) * VS + (iy - 1)) * VS + (iz - 1);

    float f0 = feats[idx * 3 + 0];
    float f1 = feats[idx * 3 + 1];
    float f2 = feats[idx * 3 + 2];

    float* s = &g_sum[(size_t)cell * 8];
    // Two v4 return-less reductions per point; count folded into ch6.
    asm volatile("red.global.add.v4.f32 [%0], {%1, %2, %3, %4};"
                 :: "l"(s), "f"(x), "f"(y), "f"(z), "f"(f0) : "memory");
    asm volatile("red.global.add.v4.f32 [%0], {%1, %2, %3, %4};"
                 :: "l"(s + 4), "f"(f1), "f"(f2), "f"(1.0f), "f"(0.0f) : "memory");
    // Benign-race occupancy flag (all writers store 1).
    g_flag[cell] = 1;
}

__global__ void __launch_bounds__(256) finalize_kernel(float* __restrict__ out)
{
    __shared__ __align__(16) float stage[NBUF][2560];  // 3 x 10 KB

    int blockBase = blockIdx.x * CPB;

#pragma unroll
    for (int g = 0; g < GROUPS; g++) {
        int buf = g % NBUF;
        int cell = blockBase + g * 256 + threadIdx.x;

        // Decode (i, j, k) within the batch's 100^3 block.
        int k = cell % VS;
        int t = cell / VS;
        int j = t % VS;
        int i = (t / VS) % VS;

        unsigned char flag = g_flag[cell];

        float v0 = 0.f, v1 = 0.f, v2 = 0.f, v3 = 0.f, v4 = 0.f, v5 = 0.f;
        float occ = 0.f;
        if (flag) {
            float4* sp = (float4*)&g_sum[(size_t)cell * 8];
            float4 a = sp[0];
            float4 b4 = sp[1];
            float cnt = b4.z;  // count accumulated in ch6
            v0 = a.x / cnt;
            v1 = a.y / cnt;
            v2 = a.z / cnt;
            v3 = a.w / cnt;
            v4 = b4.x / cnt;
            v5 = b4.y / cnt;
            occ = 1.0f;
            // Self-clean scratch for the next graph replay.
            float4 z4 = make_float4(0.f, 0.f, 0.f, 0.f);
            sp[0] = z4;
            sp[1] = z4;
            g_flag[cell] = 0;
        }

        // Before reusing this buffer (last used at group g-NBUF), allow up to
        // NBUF-1 = 2 bulk stores outstanding.
        if (g >= NBUF) {
            if (threadIdx.x == 0) {
                asm volatile("cp.async.bulk.wait_group 2;" ::: "memory");
            }
            __syncthreads();
        }

        float* st = stage[buf] + threadIdx.x * 10;
        st[0] = v0;
        st[1] = v1;
        st[2] = v2;
        st[3] = v3;
        st[4] = v4;
        st[5] = v5;
        st[6] = (float)i * 0.01f;
        st[7] = (float)j * 0.01f;
        st[8] = (float)k * 0.01f;
        st[9] = occ;
        __syncthreads();

        if (threadIdx.x == 0) {
            uint32_t smem_addr = (uint32_t)__cvta_generic_to_shared(stage[buf]);
            float* dst = out + (size_t)(blockBase + g * 256) * 10;
            asm volatile("fence.proxy.async.shared::cta;" ::: "memory");
            asm volatile("cp.async.bulk.global.shared::cta.bulk_group [%0], [%1], %2;"
                         :: "l"(dst), "r"(smem_addr), "r"(10240) : "memory");
            asm volatile("cp.async.bulk.commit_group;" ::: "memory");
        }
    }

    // Keep the CTA (and its smem) alive until all stores drain.
    if (threadIdx.x == 0) {
        asm volatile("cp.async.bulk.wait_group 0;" ::: "memory");
    }
}

extern "C" void kernel_launch(void* const* d_in, const int* in_sizes, int n_in,
                              void* d_out, int out_size)
{
    const float* coords = (const float*)d_in[0];
    const float* feats  = (const float*)d_in[1];
    float* out = (float*)d_out;

    scatter_kernel<<<(NPTS + 255) / 256, 256>>>(coords, feats);
    finalize_kernel<<<NBLK, 256>>>(out);  // 3125 blocks x 2560 cells
}

// round 14
// speedup vs baseline: 2.1710x; 1.1442x over previous
#include <cuda_runtime.h>
#include <cstdint>

#define VS 100
#define BATCH 8
#define NUM_COORDS 65536
#define NPTS (BATCH * NUM_COORDS)          // 524288
#define NCELLS (BATCH * VS * VS * VS)      // 8,000,000

#define GROUPS 5                            // cells per block = GROUPS*256 = 1280
#define CPB (GROUPS * 256)
#define NBLK (NCELLS / CPB)                 // 6250, exact

// Scratch: zero-initialized at module load; finalize re-zeroes exactly the
// occupied cells it consumes -> graph replays deterministic, no clear pass.
// g_sum ch0..5 = sums(x,y,z,f0,f1,f2), ch6 = count, ch7 = 0.
__device__ float g_sum[(size_t)NCELLS * 8];   // 256 MB
__device__ unsigned char g_flag[NCELLS];      // 8 MB occupancy flags

__global__ void __launch_bounds__(256) scatter_kernel(
    const float* __restrict__ coords,
    const float* __restrict__ feats)
{
    int idx = blockIdx.x * blockDim.x + threadIdx.x;
    if (idx >= NPTS) return;

    float x = coords[idx * 3 + 0];
    float y = coords[idx * 3 + 1];
    float z = coords[idx * 3 + 2];

    // Reference constants collapse in f32: res = denom = 0.01f, shift = -0.01f
    const float shift = 0.01f;
    const float denom = 0.01f;
    int ix = (int)floorf((x + shift) / denom);
    int iy = (int)floorf((y + shift) / denom);
    int iz = (int)floorf((z + shift) / denom);

    if (ix < 1 || ix > VS || iy < 1 || iy > VS || iz < 1 || iz > VS) return;

    int b = idx >> 16;  // NUM_COORDS = 65536
    int cell = ((b * VS + (ix - 1)) * VS + (iy - 1)) * VS + (iz - 1);

    float f0 = feats[idx * 3 + 0];
    float f1 = feats[idx * 3 + 1];
    float f2 = feats[idx * 3 + 2];

    float* s = &g_sum[(size_t)cell * 8];
    // Two v4 return-less reductions per point; count folded into ch6.
    asm volatile("red.global.add.v4.f32 [%0], {%1, %2, %3, %4};"
                 :: "l"(s), "f"(x), "f"(y), "f"(z), "f"(f0) : "memory");
    asm volatile("red.global.add.v4.f32 [%0], {%1, %2, %3, %4};"
                 :: "l"(s + 4), "f"(f1), "f"(f2), "f"(1.0f), "f"(0.0f) : "memory");
    // Benign-race occupancy flag (all writers store 1).
    g_flag[cell] = 1;
}

__global__ void __launch_bounds__(256) finalize_kernel(float* __restrict__ out)
{
    __shared__ __align__(16) float stage[2][2560];  // 2 x 10 KB double buffer

    int blockBase = blockIdx.x * CPB;

    // Prefetch all groups' flags up front: 5 independent coalesced loads
    // (MLP=5). Removes the flag->sum serial dependency inside each group.
    unsigned char fl[GROUPS];
#pragma unroll
    for (int g = 0; g < GROUPS; g++) {
        fl[g] = g_flag[blockBase + g * 256 + threadIdx.x];
    }

#pragma unroll
    for (int g = 0; g < GROUPS; g++) {
        int buf = g & 1;
        int cell = blockBase + g * 256 + threadIdx.x;

        // Decode (i, j, k) within the batch's 100^3 block.
        int k = cell % VS;
        int t = cell / VS;
        int j = t % VS;
        int i = (t / VS) % VS;

        unsigned char flag = fl[g];

        float v0 = 0.f, v1 = 0.f, v2 = 0.f, v3 = 0.f, v4 = 0.f, v5 = 0.f;
        float occ = 0.f;
        if (flag) {
            float4* sp = (float4*)&g_sum[(size_t)cell * 8];
            float4 a = sp[0];
            float4 b4 = sp[1];
            float cnt = b4.z;  // count accumulated in ch6
            v0 = a.x / cnt;
            v1 = a.y / cnt;
            v2 = a.z / cnt;
            v3 = a.w / cnt;
            v4 = b4.x / cnt;
            v5 = b4.y / cnt;
            occ = 1.0f;
            // Self-clean scratch for the next graph replay.
            float4 z4 = make_float4(0.f, 0.f, 0.f, 0.f);
            sp[0] = z4;
            sp[1] = z4;
            g_flag[cell] = 0;
        }

        // Drain the store issued on this buffer two groups ago before reuse.
        if (g >= 2) {
            if (threadIdx.x == 0) {
                asm volatile("cp.async.bulk.wait_group 1;" ::: "memory");
            }
            __syncthreads();
        }

        float* st = stage[buf] + threadIdx.x * 10;
        st[0] = v0;
        st[1] = v1;
        st[2] = v2;
        st[3] = v3;
        st[4] = v4;
        st[5] = v5;
        st[6] = (float)i * 0.01f;
        st[7] = (float)j * 0.01f;
        st[8] = (float)k * 0.01f;
        st[9] = occ;
        __syncthreads();

        if (threadIdx.x == 0) {
            uint32_t smem_addr = (uint32_t)__cvta_generic_to_shared(stage[buf]);
            float* dst = out + (size_t)(blockBase + g * 256) * 10;
            asm volatile("fence.proxy.async.shared::cta;" ::: "memory");
            asm volatile("cp.async.bulk.global.shared::cta.bulk_group [%0], [%1], %2;"
                         :: "l"(dst), "r"(smem_addr), "r"(10240) : "memory");
            asm volatile("cp.async.bulk.commit_group;" ::: "memory");
        }
    }

    // Keep the CTA (and its smem) alive until all stores drain.
    if (threadIdx.x == 0) {
        asm volatile("cp.async.bulk.wait_group 0;" ::: "memory");
    }
}

extern "C" void kernel_launch(void* const* d_in, const int* in_sizes, int n_in,
                              void* d_out, int out_size)
{
    const float* coords = (const float*)d_in[0];
    const float* feats  = (const float*)d_in[1];
    float* out = (float*)d_out;

    scatter_kernel<<<(NPTS + 255) / 256, 256>>>(coords, feats);
    finalize_kernel<<<NBLK, 256>>>(out);  // 6250 blocks x 1280 cells
}